// round 7
// baseline (speedup 1.0000x reference)
#include <cuda_runtime.h>
#include <cuda_bf16.h>
#include <cstdint>

// ---------------------------------------------------------------------------
// BiARMA (2-layer ARMA GCN), N=100000, E=1e6, 128 -> 64 -> 40.
//
// dinv = rsqrt(deg(col)), 0 where deg==0
// g1   = dinv * (x @ W1i)            S1[c] = sum_{edges into c} g1[row]
// out1 = relu(dinv*S1 + x @ W1r + b1)
// g2   = dinv * (out1 @ W2i)         S2[c] = sum g2[row]
// out  = relu(dinv*S2 + out1 @ W2r + b2)
//
// GEMMs: mma.sync.m16n8k16 bf16, 2-term split (Ah*Bh + Ah*Bl + Al*Bh).
// Aggregation: CSR-by-target (count -> scan -> bucket) then atomic-free
// gather-sum (replaces REDG-floor-bound scatter atomics).
// ---------------------------------------------------------------------------

static constexpr int MAXN = 100000;
static constexpr int MAXE = 1000000;

__device__ float g_dinv[MAXN];
__device__ int   g_cnt [MAXN];        // in-degree
__device__ int   g_cur [MAXN];        // bucket cursors
__device__ int   g_off [MAXN + 1];    // CSR offsets
__device__ int   g_perm[MAXE];        // source node per CSR slot
__device__ float g_bufA[MAXN * 64];   // g1, later out1
__device__ float g_bufB[MAXN * 80];   // S1 [0,64N); then g2 [0,40N) + S2 [40N,80N)

// ---------------------------------------------------------------------------
__global__ void deg_kernel(const int* __restrict__ col, int* __restrict__ cnt, int E) {
    int i = blockIdx.x * blockDim.x + threadIdx.x;
    if (i < E) atomicAdd(&cnt[col[i]], 1);
}

__global__ void dinv_kernel(const int* __restrict__ cnt, float* __restrict__ dinv, int N) {
    int i = blockIdx.x * blockDim.x + threadIdx.x;
    if (i < N) {
        int c = cnt[i];
        dinv[i] = (c > 0) ? rsqrtf((float)c) : 0.0f;
    }
}

// Single-block exclusive scan of cnt[0..N) -> off, cur; off[N] = E.
__global__ void __launch_bounds__(1024)
scan_kernel(const int* __restrict__ cnt, int* __restrict__ off,
            int* __restrict__ cur, int N)
{
    __shared__ int part[1024];
    const int tid   = threadIdx.x;
    const int chunk = (N + 1023) / 1024;
    const int s = tid * chunk;
    const int e = min(s + chunk, N);

    int sum = 0;
    for (int i = s; i < e; i++) sum += cnt[i];
    part[tid] = sum;
    __syncthreads();

    int own = sum;
    for (int d = 1; d < 1024; d <<= 1) {
        int t = (tid >= d) ? part[tid - d] : 0;
        __syncthreads();
        part[tid] += t;
        __syncthreads();
    }
    int run = part[tid] - own;   // exclusive prefix

    for (int i = s; i < e; i++) {
        off[i] = run;
        cur[i] = run;
        run += cnt[i];
    }
    if (s < N && e == N) off[N] = run;
}

__global__ void permute_kernel(const int* __restrict__ row, const int* __restrict__ col,
                               int* __restrict__ cur, int* __restrict__ perm, int E)
{
    int i = blockIdx.x * blockDim.x + threadIdx.x;
    if (i < E) {
        int pos = atomicAdd(&cur[col[i]], 1);
        perm[pos] = row[i];
    }
}

// ---------------------------------------------------------------------------
// Atomic-free CSR aggregation: S[n] = sum over incoming edges of G[perm[i]].
// Thread = (node, float4-chunk).  F = 4*FQ floats per node.
// ---------------------------------------------------------------------------
template <int FQ>
__global__ void agg_csr(const int* __restrict__ off, const int* __restrict__ perm,
                        const float* __restrict__ G, float* __restrict__ S, int total)
{
    int idx = blockIdx.x * blockDim.x + threadIdx.x;
    if (idx >= total) return;
    int node = idx / FQ;
    int c    = idx - node * FQ;
    int s = __ldg(off + node);
    int e = __ldg(off + node + 1);

    const float4* G4 = reinterpret_cast<const float4*>(G);
    float4 acc = make_float4(0.f, 0.f, 0.f, 0.f);

    int i = s;
    for (; i + 1 < e; i += 2) {
        int r0 = __ldg(perm + i);
        int r1 = __ldg(perm + i + 1);
        float4 v0 = __ldg(G4 + (size_t)r0 * FQ + c);
        float4 v1 = __ldg(G4 + (size_t)r1 * FQ + c);
        acc.x += v0.x; acc.y += v0.y; acc.z += v0.z; acc.w += v0.w;
        acc.x += v1.x; acc.y += v1.y; acc.z += v1.z; acc.w += v1.w;
    }
    if (i < e) {
        int r0 = __ldg(perm + i);
        float4 v0 = __ldg(G4 + (size_t)r0 * FQ + c);
        acc.x += v0.x; acc.y += v0.y; acc.z += v0.z; acc.w += v0.w;
    }
    reinterpret_cast<float4*>(S)[(size_t)node * FQ + c] = acc;
}

// ---------------------------------------------------------------------------
// Tensor-core GEMM with epilogue (unchanged from round 4).
// ---------------------------------------------------------------------------
#define MMA_BF16(c_, a_, b0_, b1_)                                          \
    asm volatile("mma.sync.aligned.m16n8k16.row.col.f32.bf16.bf16.f32 "     \
                 "{%0,%1,%2,%3}, {%4,%5,%6,%7}, {%8,%9}, {%0,%1,%2,%3};"    \
                 : "+f"((c_)[0]), "+f"((c_)[1]), "+f"((c_)[2]), "+f"((c_)[3]) \
                 : "r"((a_)[0]), "r"((a_)[1]), "r"((a_)[2]), "r"((a_)[3]),  \
                   "r"(b0_), "r"(b1_))

__device__ __forceinline__ void split_bf16(float v, __nv_bfloat16& h, __nv_bfloat16& l) {
    h = __float2bfloat16(v);
    l = __float2bfloat16(v - __bfloat162float(h));
}

template <int K, int NC, bool POST>
__global__ void __launch_bounds__(128)
gemm_mma(const float* __restrict__ X, const float* __restrict__ W,
         const float* __restrict__ Bias, const float* __restrict__ dinv,
         const float* __restrict__ S, float* __restrict__ O, int N)
{
    constexpr int SA = K + 8;
    constexpr int NT = NC / 8;

    extern __shared__ __nv_bfloat16 sm[];
    __nv_bfloat16* Ah = sm;
    __nv_bfloat16* Al = Ah + 128 * SA;
    __nv_bfloat16* Bh = Al + 128 * SA;
    __nv_bfloat16* Bl = Bh + NC * SA;

    const int tid  = threadIdx.x;
    const int base = blockIdx.x * 128;

    for (int idx = tid; idx < 128 * (K / 4); idx += 128) {
        int row = idx / (K / 4);
        int c4  = idx - row * (K / 4);
        int node = base + row;
        float4 v = (node < N) ? __ldg(reinterpret_cast<const float4*>(X + (size_t)node * K + c4 * 4))
                              : make_float4(0.f, 0.f, 0.f, 0.f);
        float vs[4] = {v.x, v.y, v.z, v.w};
        __nv_bfloat16 h[4], l[4];
#pragma unroll
        for (int j = 0; j < 4; j++) split_bf16(vs[j], h[j], l[j]);
        __nv_bfloat162* ph = reinterpret_cast<__nv_bfloat162*>(Ah + row * SA + c4 * 4);
        __nv_bfloat162* pl = reinterpret_cast<__nv_bfloat162*>(Al + row * SA + c4 * 4);
        ph[0] = __nv_bfloat162(h[0], h[1]); ph[1] = __nv_bfloat162(h[2], h[3]);
        pl[0] = __nv_bfloat162(l[0], l[1]); pl[1] = __nv_bfloat162(l[2], l[3]);
    }
    for (int i = tid; i < K * NC; i += 128) {
        int k = i / NC, n = i - k * NC;
        __nv_bfloat16 h, l;
        split_bf16(W[i], h, l);
        Bh[n * SA + k] = h;
        Bl[n * SA + k] = l;
    }
    __syncthreads();

    const int warp = tid >> 5, lane = tid & 31;
    const int g = lane >> 2, t = lane & 3;

    float acc[2][NT][4];
#pragma unroll
    for (int mt = 0; mt < 2; mt++)
#pragma unroll
        for (int nt = 0; nt < NT; nt++)
#pragma unroll
            for (int j = 0; j < 4; j++) acc[mt][nt][j] = 0.0f;

#pragma unroll 2
    for (int ks = 0; ks < K; ks += 16) {
        const int k0 = ks + t * 2;
        uint32_t a[2][2][4];
#pragma unroll
        for (int mt = 0; mt < 2; mt++) {
            int r0 = warp * 32 + mt * 16 + g;
            a[mt][0][0] = *reinterpret_cast<const uint32_t*>(Ah + r0 * SA + k0);
            a[mt][0][1] = *reinterpret_cast<const uint32_t*>(Ah + (r0 + 8) * SA + k0);
            a[mt][0][2] = *reinterpret_cast<const uint32_t*>(Ah + r0 * SA + k0 + 8);
            a[mt][0][3] = *reinterpret_cast<const uint32_t*>(Ah + (r0 + 8) * SA + k0 + 8);
            a[mt][1][0] = *reinterpret_cast<const uint32_t*>(Al + r0 * SA + k0);
            a[mt][1][1] = *reinterpret_cast<const uint32_t*>(Al + (r0 + 8) * SA + k0);
            a[mt][1][2] = *reinterpret_cast<const uint32_t*>(Al + r0 * SA + k0 + 8);
            a[mt][1][3] = *reinterpret_cast<const uint32_t*>(Al + (r0 + 8) * SA + k0 + 8);
        }
#pragma unroll
        for (int nt = 0; nt < NT; nt++) {
            int n0 = nt * 8 + g;
            uint32_t bh0 = *reinterpret_cast<const uint32_t*>(Bh + n0 * SA + k0);
            uint32_t bh1 = *reinterpret_cast<const uint32_t*>(Bh + n0 * SA + k0 + 8);
            uint32_t bl0 = *reinterpret_cast<const uint32_t*>(Bl + n0 * SA + k0);
            uint32_t bl1 = *reinterpret_cast<const uint32_t*>(Bl + n0 * SA + k0 + 8);
#pragma unroll
            for (int mt = 0; mt < 2; mt++) {
                MMA_BF16(acc[mt][nt], a[mt][0], bh0, bh1);
                MMA_BF16(acc[mt][nt], a[mt][0], bl0, bl1);
                MMA_BF16(acc[mt][nt], a[mt][1], bh0, bh1);
            }
        }
    }

#pragma unroll
    for (int mt = 0; mt < 2; mt++) {
        int r0 = base + warp * 32 + mt * 16 + g;
        int r1 = r0 + 8;
        float dv0 = (r0 < N) ? dinv[r0] : 0.0f;
        float dv1 = (r1 < N) ? dinv[r1] : 0.0f;
#pragma unroll
        for (int nt = 0; nt < NT; nt++) {
            int col = nt * 8 + t * 2;
            const float* a4 = acc[mt][nt];
            if (POST) {
                float2 bb = *reinterpret_cast<const float2*>(Bias + col);
                if (r0 < N) {
                    float2 s = *reinterpret_cast<const float2*>(S + (size_t)r0 * NC + col);
                    float2 o;
                    o.x = fmaxf(fmaf(dv0, s.x, a4[0] + bb.x), 0.0f);
                    o.y = fmaxf(fmaf(dv0, s.y, a4[1] + bb.y), 0.0f);
                    *reinterpret_cast<float2*>(O + (size_t)r0 * NC + col) = o;
                }
                if (r1 < N) {
                    float2 s = *reinterpret_cast<const float2*>(S + (size_t)r1 * NC + col);
                    float2 o;
                    o.x = fmaxf(fmaf(dv1, s.x, a4[2] + bb.x), 0.0f);
                    o.y = fmaxf(fmaf(dv1, s.y, a4[3] + bb.y), 0.0f);
                    *reinterpret_cast<float2*>(O + (size_t)r1 * NC + col) = o;
                }
            } else {
                if (r0 < N) {
                    float2 o = make_float2(a4[0] * dv0, a4[1] * dv0);
                    *reinterpret_cast<float2*>(O + (size_t)r0 * NC + col) = o;
                }
                if (r1 < N) {
                    float2 o = make_float2(a4[2] * dv1, a4[3] * dv1);
                    *reinterpret_cast<float2*>(O + (size_t)r1 * NC + col) = o;
                }
            }
        }
    }
}

// ---------------------------------------------------------------------------
extern "C" void kernel_launch(void* const* d_in, const int* in_sizes, int n_in,
                              void* d_out, int out_size)
{
    const float* x   = (const float*)d_in[0];
    const int*   ei  = (const int*)  d_in[1];
    const float* w1i = (const float*)d_in[2];
    const float* w1r = (const float*)d_in[3];
    const float* b1  = (const float*)d_in[4];
    const float* w2i = (const float*)d_in[5];
    const float* w2r = (const float*)d_in[6];
    const float* b2  = (const float*)d_in[7];
    float* out = (float*)d_out;

    const int E = in_sizes[1] / 2;
    const int N = out_size / 40;
    const int* row = ei;
    const int* col = ei + E;

    float *pdinv, *pA, *pB;
    int *pcnt, *pcur, *poff, *pperm;
    cudaGetSymbolAddress((void**)&pdinv, g_dinv);
    cudaGetSymbolAddress((void**)&pcnt,  g_cnt);
    cudaGetSymbolAddress((void**)&pcur,  g_cur);
    cudaGetSymbolAddress((void**)&poff,  g_off);
    cudaGetSymbolAddress((void**)&pperm, g_perm);
    cudaGetSymbolAddress((void**)&pA,    g_bufA);
    cudaGetSymbolAddress((void**)&pB,    g_bufB);

    // ---- CSR build ----
    cudaMemsetAsync(pcnt, 0, (size_t)N * sizeof(int));
    deg_kernel   <<<(E + 255) / 256, 256>>>(col, pcnt, E);
    dinv_kernel  <<<(N + 255) / 256, 256>>>(pcnt, pdinv, N);
    scan_kernel  <<<1, 1024>>>(pcnt, poff, pcur, N);
    permute_kernel<<<(E + 255) / 256, 256>>>(row, col, pcur, pperm, E);

    const int grid = (N + 127) / 128;

    // ---- Layer 1 (K=128, NC=64) ----
    const int smem1 = (2 * 128 + 2 * 64) * (128 + 8) * (int)sizeof(__nv_bfloat16);
    cudaFuncSetAttribute(gemm_mma<128, 64, false>, cudaFuncAttributeMaxDynamicSharedMemorySize, smem1);
    cudaFuncSetAttribute(gemm_mma<128, 64, true>,  cudaFuncAttributeMaxDynamicSharedMemorySize, smem1);

    // g1 = dinv * (x @ W1i) -> bufA
    gemm_mma<128, 64, false><<<grid, 128, smem1>>>(x, w1i, nullptr, pdinv, nullptr, pA, N);

    // S1 = CSR gather-sum of g1 (atomic-free, no memset needed)
    {
        int total = N * 16;
        agg_csr<16><<<(total + 255) / 256, 256>>>(poff, pperm, pA, pB, total);
    }
    // out1 = relu(dinv*S1 + x@W1r + b1) -> bufA
    gemm_mma<128, 64, true><<<grid, 128, smem1>>>(x, w1r, b1, pdinv, pB, pA, N);

    // ---- Layer 2 (K=64, NC=40) ----
    const int smem2 = (2 * 128 + 2 * 40) * (64 + 8) * (int)sizeof(__nv_bfloat16);
    float* pG2 = pB;                     // g2 in bufB[0,40N)
    float* pS2 = pB + (size_t)N * 40;    // S2 in bufB[40N,80N)

    gemm_mma<64, 40, false><<<grid, 128, smem2>>>(pA, w2i, nullptr, pdinv, nullptr, pG2, N);
    {
        int total = N * 10;
        agg_csr<10><<<(total + 255) / 256, 256>>>(poff, pperm, pG2, pS2, total);
    }
    gemm_mma<64, 40, true><<<grid, 128, smem2>>>(pA, w2r, b2, pdinv, pS2, out, N);
}

// round 9
// speedup vs baseline: 1.3038x; 1.3038x over previous
#include <cuda_runtime.h>
#include <cuda_bf16.h>
#include <cstdint>

// ---------------------------------------------------------------------------
// BiARMA (2-layer ARMA GCN), N=100000, E=1e6, 128 -> 64 -> 40.
//
// dinv = rsqrt(deg(col)), 0 where deg==0
// g1   = dinv * (x @ W1i)            S1[c] += g1[row]  (fp32 vector atomics)
// out1 = relu(dinv*S1 + x @ W1r + b1)
// g2   = dinv * (out1 @ W2i)         S2[c] += g2[row]
// out  = relu(dinv*S2 + out1 @ W2r + b2)
//
// GEMMs: mma.sync.m16n8k16 bf16, 2-term split (Ah*Bh + Ah*Bl + Al*Bh).
// Layer 1: fused dual GEMM (init+root from ONE x staging pass) that also
// zeroes S1 (no memset). Scatter: red.global.add.v4.f32 (REDG floor-bound).
//
// Scratch 77.2 MB:  dinv[N], bufA[64N] (g1->out1), R[64N] (R1; then g2),
//                   bufS[64N] (S1; then S2).
// ---------------------------------------------------------------------------

static constexpr int MAXN = 100000;

__device__ float g_dinv[MAXN];
__device__ float g_bufA[MAXN * 64];   // g1, later out1
__device__ float g_R   [MAXN * 64];   // R1 = x@W1r+b1 ; layer2: g2 in [0,40N)
__device__ float g_bufS[MAXN * 64];   // S1 ; layer2: S2 in [0,40N)

// ---------------------------------------------------------------------------
__global__ void deg_kernel(const int* __restrict__ col, float* __restrict__ deg, int E) {
    int i = blockIdx.x * blockDim.x + threadIdx.x;
    if (i < E) atomicAdd(&deg[col[i]], 1.0f);
}

__global__ void dinv_kernel(float* __restrict__ d, int N) {
    int i = blockIdx.x * blockDim.x + threadIdx.x;
    if (i < N) {
        float v = d[i];
        d[i] = (v > 0.0f) ? rsqrtf(v) : 0.0f;
    }
}

// ---------------------------------------------------------------------------
#define MMA_BF16(c_, a_, b0_, b1_)                                          \
    asm volatile("mma.sync.aligned.m16n8k16.row.col.f32.bf16.bf16.f32 "     \
                 "{%0,%1,%2,%3}, {%4,%5,%6,%7}, {%8,%9}, {%0,%1,%2,%3};"    \
                 : "+f"((c_)[0]), "+f"((c_)[1]), "+f"((c_)[2]), "+f"((c_)[3]) \
                 : "r"((a_)[0]), "r"((a_)[1]), "r"((a_)[2]), "r"((a_)[3]),  \
                   "r"(b0_), "r"(b1_))

__device__ __forceinline__ void split_bf16(float v, __nv_bfloat16& h, __nv_bfloat16& l) {
    h = __float2bfloat16(v);
    l = __float2bfloat16(v - __bfloat162float(h));
}

// ---------------------------------------------------------------------------
// Fused dual GEMM (layer 1): one staging of X; computes
//   G = dinv * (X @ Wi)      -> G
//   R = (X @ Wr) + bias      -> R
//   S = 0                    -> S   (prepares scatter target, kills memset)
// Block: 128 rows, 256 threads (8 warps; warp = 16 rows x NC cols).
// ---------------------------------------------------------------------------
template <int K, int NC>
__global__ void __launch_bounds__(256)
gemm_dual_mma(const float* __restrict__ X,
              const float* __restrict__ Wi, const float* __restrict__ Wr,
              const float* __restrict__ Bias, const float* __restrict__ dinv,
              float* __restrict__ G, float* __restrict__ R,
              float* __restrict__ S, int N)
{
    constexpr int SA = K + 8;
    constexpr int NT = NC / 8;

    extern __shared__ __nv_bfloat16 sm[];
    __nv_bfloat16* Ah  = sm;                    // [128][SA]
    __nv_bfloat16* Al  = Ah  + 128 * SA;
    __nv_bfloat16* Bhi = Al  + 128 * SA;        // [NC][SA] init weights (n-major)
    __nv_bfloat16* Bli = Bhi + NC * SA;
    __nv_bfloat16* Bhr = Bli + NC * SA;         // root weights
    __nv_bfloat16* Blr = Bhr + NC * SA;

    const int tid  = threadIdx.x;
    const int base = blockIdx.x * 128;

    // stage X (fp32 -> bf16 hi/lo)
    for (int idx = tid; idx < 128 * (K / 4); idx += 256) {
        int row = idx / (K / 4);
        int c4  = idx - row * (K / 4);
        int node = base + row;
        float4 v = (node < N) ? __ldg(reinterpret_cast<const float4*>(X + (size_t)node * K + c4 * 4))
                              : make_float4(0.f, 0.f, 0.f, 0.f);
        float vs[4] = {v.x, v.y, v.z, v.w};
        __nv_bfloat16 h[4], l[4];
#pragma unroll
        for (int j = 0; j < 4; j++) split_bf16(vs[j], h[j], l[j]);
        __nv_bfloat162* ph = reinterpret_cast<__nv_bfloat162*>(Ah + row * SA + c4 * 4);
        __nv_bfloat162* pl = reinterpret_cast<__nv_bfloat162*>(Al + row * SA + c4 * 4);
        ph[0] = __nv_bfloat162(h[0], h[1]); ph[1] = __nv_bfloat162(h[2], h[3]);
        pl[0] = __nv_bfloat162(l[0], l[1]); pl[1] = __nv_bfloat162(l[2], l[3]);
    }
    // stage both weight matrices transposed (n-major)
    for (int i = tid; i < K * NC; i += 256) {
        int k = i / NC, n = i - k * NC;
        __nv_bfloat16 h, l;
        split_bf16(Wi[i], h, l); Bhi[n * SA + k] = h; Bli[n * SA + k] = l;
        split_bf16(Wr[i], h, l); Bhr[n * SA + k] = h; Blr[n * SA + k] = l;
    }
    __syncthreads();

    const int warp = tid >> 5, lane = tid & 31;
    const int g = lane >> 2, t = lane & 3;
    const int r0l = warp * 16 + g;          // local rows r0l, r0l+8

    float ai[NT][4], ar[NT][4];
#pragma unroll
    for (int nt = 0; nt < NT; nt++)
#pragma unroll
        for (int j = 0; j < 4; j++) { ai[nt][j] = 0.0f; ar[nt][j] = 0.0f; }

    for (int ks = 0; ks < K; ks += 16) {
        const int k0 = ks + t * 2;
        uint32_t a[2][4];     // [hi/lo][reg]
        a[0][0] = *reinterpret_cast<const uint32_t*>(Ah + r0l * SA + k0);
        a[0][1] = *reinterpret_cast<const uint32_t*>(Ah + (r0l + 8) * SA + k0);
        a[0][2] = *reinterpret_cast<const uint32_t*>(Ah + r0l * SA + k0 + 8);
        a[0][3] = *reinterpret_cast<const uint32_t*>(Ah + (r0l + 8) * SA + k0 + 8);
        a[1][0] = *reinterpret_cast<const uint32_t*>(Al + r0l * SA + k0);
        a[1][1] = *reinterpret_cast<const uint32_t*>(Al + (r0l + 8) * SA + k0);
        a[1][2] = *reinterpret_cast<const uint32_t*>(Al + r0l * SA + k0 + 8);
        a[1][3] = *reinterpret_cast<const uint32_t*>(Al + (r0l + 8) * SA + k0 + 8);
#pragma unroll
        for (int nt = 0; nt < NT; nt++) {
            int n0 = nt * 8 + g;
            uint32_t bh0 = *reinterpret_cast<const uint32_t*>(Bhi + n0 * SA + k0);
            uint32_t bh1 = *reinterpret_cast<const uint32_t*>(Bhi + n0 * SA + k0 + 8);
            uint32_t bl0 = *reinterpret_cast<const uint32_t*>(Bli + n0 * SA + k0);
            uint32_t bl1 = *reinterpret_cast<const uint32_t*>(Bli + n0 * SA + k0 + 8);
            MMA_BF16(ai[nt], a[0], bh0, bh1);
            MMA_BF16(ai[nt], a[0], bl0, bl1);
            MMA_BF16(ai[nt], a[1], bh0, bh1);
            uint32_t ch0 = *reinterpret_cast<const uint32_t*>(Bhr + n0 * SA + k0);
            uint32_t ch1 = *reinterpret_cast<const uint32_t*>(Bhr + n0 * SA + k0 + 8);
            uint32_t cl0 = *reinterpret_cast<const uint32_t*>(Blr + n0 * SA + k0);
            uint32_t cl1 = *reinterpret_cast<const uint32_t*>(Blr + n0 * SA + k0 + 8);
            MMA_BF16(ar[nt], a[0], ch0, ch1);
            MMA_BF16(ar[nt], a[0], cl0, cl1);
            MMA_BF16(ar[nt], a[1], ch0, ch1);
        }
    }

    // epilogue: G = acc_i*dinv, R = acc_r + bias, S = 0
    const int r0 = base + r0l;
    const int r1 = r0 + 8;
    const float dv0 = (r0 < N) ? dinv[r0] : 0.0f;
    const float dv1 = (r1 < N) ? dinv[r1] : 0.0f;
#pragma unroll
    for (int nt = 0; nt < NT; nt++) {
        int col = nt * 8 + t * 2;
        float2 bb = *reinterpret_cast<const float2*>(Bias + col);
        float2 z = make_float2(0.f, 0.f);
        if (r0 < N) {
            *reinterpret_cast<float2*>(G + (size_t)r0 * NC + col) =
                make_float2(ai[nt][0] * dv0, ai[nt][1] * dv0);
            *reinterpret_cast<float2*>(R + (size_t)r0 * NC + col) =
                make_float2(ar[nt][0] + bb.x, ar[nt][1] + bb.y);
            *reinterpret_cast<float2*>(S + (size_t)r0 * NC + col) = z;
        }
        if (r1 < N) {
            *reinterpret_cast<float2*>(G + (size_t)r1 * NC + col) =
                make_float2(ai[nt][2] * dv1, ai[nt][3] * dv1);
            *reinterpret_cast<float2*>(R + (size_t)r1 * NC + col) =
                make_float2(ar[nt][2] + bb.x, ar[nt][3] + bb.y);
            *reinterpret_cast<float2*>(S + (size_t)r1 * NC + col) = z;
        }
    }
}

// ---------------------------------------------------------------------------
// Single GEMM (layer 2).  POST=false: O = dinv*(X@W), and zero S.
//                         POST=true : O = relu(dinv*S + X@W + b)
// Block: 128 rows, 128 threads (4 warps; warp = 32 rows).
// ---------------------------------------------------------------------------
template <int K, int NC, bool POST>
__global__ void __launch_bounds__(128)
gemm_mma(const float* __restrict__ X, const float* __restrict__ W,
         const float* __restrict__ Bias, const float* __restrict__ dinv,
         float* __restrict__ S, float* __restrict__ O, int N)
{
    constexpr int SA = K + 8;
    constexpr int NT = NC / 8;

    extern __shared__ __nv_bfloat16 sm[];
    __nv_bfloat16* Ah = sm;
    __nv_bfloat16* Al = Ah + 128 * SA;
    __nv_bfloat16* Bh = Al + 128 * SA;
    __nv_bfloat16* Bl = Bh + NC * SA;

    const int tid  = threadIdx.x;
    const int base = blockIdx.x * 128;

    for (int idx = tid; idx < 128 * (K / 4); idx += 128) {
        int row = idx / (K / 4);
        int c4  = idx - row * (K / 4);
        int node = base + row;
        float4 v = (node < N) ? __ldg(reinterpret_cast<const float4*>(X + (size_t)node * K + c4 * 4))
                              : make_float4(0.f, 0.f, 0.f, 0.f);
        float vs[4] = {v.x, v.y, v.z, v.w};
        __nv_bfloat16 h[4], l[4];
#pragma unroll
        for (int j = 0; j < 4; j++) split_bf16(vs[j], h[j], l[j]);
        __nv_bfloat162* ph = reinterpret_cast<__nv_bfloat162*>(Ah + row * SA + c4 * 4);
        __nv_bfloat162* pl = reinterpret_cast<__nv_bfloat162*>(Al + row * SA + c4 * 4);
        ph[0] = __nv_bfloat162(h[0], h[1]); ph[1] = __nv_bfloat162(h[2], h[3]);
        pl[0] = __nv_bfloat162(l[0], l[1]); pl[1] = __nv_bfloat162(l[2], l[3]);
    }
    for (int i = tid; i < K * NC; i += 128) {
        int k = i / NC, n = i - k * NC;
        __nv_bfloat16 h, l;
        split_bf16(W[i], h, l);
        Bh[n * SA + k] = h;
        Bl[n * SA + k] = l;
    }
    __syncthreads();

    const int warp = tid >> 5, lane = tid & 31;
    const int g = lane >> 2, t = lane & 3;

    float acc[2][NT][4];
#pragma unroll
    for (int mt = 0; mt < 2; mt++)
#pragma unroll
        for (int nt = 0; nt < NT; nt++)
#pragma unroll
            for (int j = 0; j < 4; j++) acc[mt][nt][j] = 0.0f;

#pragma unroll 2
    for (int ks = 0; ks < K; ks += 16) {
        const int k0 = ks + t * 2;
        uint32_t a[2][2][4];
#pragma unroll
        for (int mt = 0; mt < 2; mt++) {
            int r0 = warp * 32 + mt * 16 + g;
            a[mt][0][0] = *reinterpret_cast<const uint32_t*>(Ah + r0 * SA + k0);
            a[mt][0][1] = *reinterpret_cast<const uint32_t*>(Ah + (r0 + 8) * SA + k0);
            a[mt][0][2] = *reinterpret_cast<const uint32_t*>(Ah + r0 * SA + k0 + 8);
            a[mt][0][3] = *reinterpret_cast<const uint32_t*>(Ah + (r0 + 8) * SA + k0 + 8);
            a[mt][1][0] = *reinterpret_cast<const uint32_t*>(Al + r0 * SA + k0);
            a[mt][1][1] = *reinterpret_cast<const uint32_t*>(Al + (r0 + 8) * SA + k0);
            a[mt][1][2] = *reinterpret_cast<const uint32_t*>(Al + r0 * SA + k0 + 8);
            a[mt][1][3] = *reinterpret_cast<const uint32_t*>(Al + (r0 + 8) * SA + k0 + 8);
        }
#pragma unroll
        for (int nt = 0; nt < NT; nt++) {
            int n0 = nt * 8 + g;
            uint32_t bh0 = *reinterpret_cast<const uint32_t*>(Bh + n0 * SA + k0);
            uint32_t bh1 = *reinterpret_cast<const uint32_t*>(Bh + n0 * SA + k0 + 8);
            uint32_t bl0 = *reinterpret_cast<const uint32_t*>(Bl + n0 * SA + k0);
            uint32_t bl1 = *reinterpret_cast<const uint32_t*>(Bl + n0 * SA + k0 + 8);
#pragma unroll
            for (int mt = 0; mt < 2; mt++) {
                MMA_BF16(acc[mt][nt], a[mt][0], bh0, bh1);
                MMA_BF16(acc[mt][nt], a[mt][0], bl0, bl1);
                MMA_BF16(acc[mt][nt], a[mt][1], bh0, bh1);
            }
        }
    }

#pragma unroll
    for (int mt = 0; mt < 2; mt++) {
        int r0 = base + warp * 32 + mt * 16 + g;
        int r1 = r0 + 8;
        float dv0 = (r0 < N) ? dinv[r0] : 0.0f;
        float dv1 = (r1 < N) ? dinv[r1] : 0.0f;
#pragma unroll
        for (int nt = 0; nt < NT; nt++) {
            int col = nt * 8 + t * 2;
            const float* a4 = acc[mt][nt];
            if (POST) {
                float2 bb = *reinterpret_cast<const float2*>(Bias + col);
                if (r0 < N) {
                    float2 s = *reinterpret_cast<const float2*>(S + (size_t)r0 * NC + col);
                    float2 o;
                    o.x = fmaxf(fmaf(dv0, s.x, a4[0] + bb.x), 0.0f);
                    o.y = fmaxf(fmaf(dv0, s.y, a4[1] + bb.y), 0.0f);
                    *reinterpret_cast<float2*>(O + (size_t)r0 * NC + col) = o;
                }
                if (r1 < N) {
                    float2 s = *reinterpret_cast<const float2*>(S + (size_t)r1 * NC + col);
                    float2 o;
                    o.x = fmaxf(fmaf(dv1, s.x, a4[2] + bb.x), 0.0f);
                    o.y = fmaxf(fmaf(dv1, s.y, a4[3] + bb.y), 0.0f);
                    *reinterpret_cast<float2*>(O + (size_t)r1 * NC + col) = o;
                }
            } else {
                float2 z = make_float2(0.f, 0.f);
                if (r0 < N) {
                    *reinterpret_cast<float2*>(O + (size_t)r0 * NC + col) =
                        make_float2(a4[0] * dv0, a4[1] * dv0);
                    *reinterpret_cast<float2*>(S + (size_t)r0 * NC + col) = z;
                }
                if (r1 < N) {
                    *reinterpret_cast<float2*>(O + (size_t)r1 * NC + col) =
                        make_float2(a4[2] * dv1, a4[3] * dv1);
                    *reinterpret_cast<float2*>(S + (size_t)r1 * NC + col) = z;
                }
            }
        }
    }
}

// ---------------------------------------------------------------------------
// Edge scatter: S[col] += G[row]  (fire-and-forget vector reduction)
// ---------------------------------------------------------------------------
template <int FQ>
__global__ void scatter_add(const int* __restrict__ rowi, const int* __restrict__ coli,
                            const float* __restrict__ G, float* __restrict__ S, int total)
{
    int idx = blockIdx.x * blockDim.x + threadIdx.x;
    if (idx >= total) return;
    int e = idx / FQ;
    int c = idx - e * FQ;
    int r  = __ldg(rowi + e);
    int cl = __ldg(coli + e);
    float4 v = __ldg(reinterpret_cast<const float4*>(G + ((size_t)r * FQ + c) * 4));
    float* p = S + ((size_t)cl * FQ + c) * 4;
    asm volatile("red.global.add.v4.f32 [%0], {%1,%2,%3,%4};"
                 :: "l"(p), "f"(v.x), "f"(v.y), "f"(v.z), "f"(v.w) : "memory");
}

// ---------------------------------------------------------------------------
// Elementwise post: O = relu(dinv[node]*S + R)   (float4)
// ---------------------------------------------------------------------------
template <int FQ>
__global__ void post_kernel(const float* __restrict__ S, const float* __restrict__ Rin,
                            const float* __restrict__ dinv, float* __restrict__ O, int total4)
{
    int idx = blockIdx.x * blockDim.x + threadIdx.x;
    if (idx >= total4) return;
    int node = idx / FQ;
    float dv = dinv[node];
    float4 s = *reinterpret_cast<const float4*>(S + (size_t)idx * 4);
    float4 r = *reinterpret_cast<const float4*>(Rin + (size_t)idx * 4);
    float4 o;
    o.x = fmaxf(fmaf(dv, s.x, r.x), 0.0f);
    o.y = fmaxf(fmaf(dv, s.y, r.y), 0.0f);
    o.z = fmaxf(fmaf(dv, s.z, r.z), 0.0f);
    o.w = fmaxf(fmaf(dv, s.w, r.w), 0.0f);
    *reinterpret_cast<float4*>(O + (size_t)idx * 4) = o;
}

// ---------------------------------------------------------------------------
extern "C" void kernel_launch(void* const* d_in, const int* in_sizes, int n_in,
                              void* d_out, int out_size)
{
    const float* x   = (const float*)d_in[0];
    const int*   ei  = (const int*)  d_in[1];
    const float* w1i = (const float*)d_in[2];
    const float* w1r = (const float*)d_in[3];
    const float* b1  = (const float*)d_in[4];
    const float* w2i = (const float*)d_in[5];
    const float* w2r = (const float*)d_in[6];
    const float* b2  = (const float*)d_in[7];
    float* out = (float*)d_out;

    const int E = in_sizes[1] / 2;
    const int N = out_size / 40;
    const int* row = ei;
    const int* col = ei + E;

    float *pdinv, *pA, *pR, *pS;
    cudaGetSymbolAddress((void**)&pdinv, g_dinv);
    cudaGetSymbolAddress((void**)&pA,    g_bufA);
    cudaGetSymbolAddress((void**)&pR,    g_R);
    cudaGetSymbolAddress((void**)&pS,    g_bufS);

    // deg -> dinv (in place)
    cudaMemsetAsync(pdinv, 0, (size_t)N * sizeof(float));
    deg_kernel <<<(E + 255) / 256, 256>>>(col, pdinv, E);
    dinv_kernel<<<(N + 255) / 256, 256>>>(pdinv, N);

    const int grid = (N + 127) / 128;

    // ---- Layer 1: fused dual GEMM (g1, R1, S1=0) ----
    const int smemD = (2 * 128 + 4 * 64) * (128 + 8) * (int)sizeof(__nv_bfloat16);  // 139264
    cudaFuncSetAttribute(gemm_dual_mma<128, 64>, cudaFuncAttributeMaxDynamicSharedMemorySize, smemD);
    gemm_dual_mma<128, 64><<<grid, 256, smemD>>>(x, w1i, w1r, b1, pdinv, pA, pR, pS, N);

    {   // S1 += g1[row] over edges
        int total = E * 16;
        scatter_add<16><<<(total + 255) / 256, 256>>>(row, col, pA, pS, total);
    }
    {   // out1 = relu(dinv*S1 + R1) -> bufA (in place over g1)
        int total4 = N * 16;
        post_kernel<16><<<(total4 + 255) / 256, 256>>>(pS, pR, pdinv, pA, total4);
    }

    // ---- Layer 2 (K=64, NC=40): g2 -> R[0,40N), S2 -> bufS[0,40N) ----
    const int smem2 = (2 * 128 + 2 * 40) * (64 + 8) * (int)sizeof(__nv_bfloat16);
    float* pG2 = pR;
    float* pS2 = pS;

    gemm_mma<64, 40, false><<<grid, 128, smem2>>>(pA, w2i, nullptr, pdinv, pS2, pG2, N);
    {
        int total = E * 10;
        scatter_add<10><<<(total + 255) / 256, 256>>>(row, col, pG2, pS2, total);
    }
    gemm_mma<64, 40, true><<<grid, 128, smem2>>>(pA, w2r, b2, pdinv, pS2, out, N);
}

// round 11
// speedup vs baseline: 1.3232x; 1.0149x over previous
#include <cuda_runtime.h>
#include <cuda_bf16.h>
#include <cstdint>

// ---------------------------------------------------------------------------
// BiARMA (2-layer ARMA GCN), N=100000, E=1e6, 128 -> 64 -> 40.
//
// deg[c] = #edges into c;  dinv = rsqrt(deg) (0 if deg==0), computed on the
// fly inside each GEMM (no dinv kernel / buffer).
// g1   = dinv * (x @ W1i)            S1[c] += g1[row]  (fp32 vector atomics)
// out1 = relu(dinv*S1 + x @ W1r + b1)
// g2   = dinv * (out1 @ W2i)         S2[c] += g2[row]
// out  = relu(dinv*S2 + out1 @ W2r + b2)
//
// GEMMs: mma.sync.m16n8k16 bf16, 2-term split (Ah*Bh + Ah*Bl + Al*Bh).
// Init GEMMs also zero the scatter target S (no memsets).
// Scatter: red.global.add.v4.f32 — measured at the REDG lane-issue floor.
// 8 graph nodes total (was 11).
//
// Scratch 67.6 MB: deg[N], bufA[64N] (g1 -> out1), bufS[64N] (S1; S2 in
// [0,40N) after S1 dies), bufG2[40N] (g2).
// ---------------------------------------------------------------------------

static constexpr int MAXN = 100000;

__device__ float g_deg  [MAXN];
__device__ float g_bufA [MAXN * 64];   // g1, later out1
__device__ float g_bufS [MAXN * 64];   // S1; later S2 in [0,40N)
__device__ float g_bufG2[MAXN * 40];   // g2

// ---------------------------------------------------------------------------
__global__ void deg_kernel(const int* __restrict__ col, float* __restrict__ deg, int E) {
    int i = blockIdx.x * blockDim.x + threadIdx.x;
    if (i < E) atomicAdd(&deg[col[i]], 1.0f);
}

// ---------------------------------------------------------------------------
#define MMA_BF16(c_, a_, b0_, b1_)                                          \
    asm volatile("mma.sync.aligned.m16n8k16.row.col.f32.bf16.bf16.f32 "     \
                 "{%0,%1,%2,%3}, {%4,%5,%6,%7}, {%8,%9}, {%0,%1,%2,%3};"    \
                 : "+f"((c_)[0]), "+f"((c_)[1]), "+f"((c_)[2]), "+f"((c_)[3]) \
                 : "r"((a_)[0]), "r"((a_)[1]), "r"((a_)[2]), "r"((a_)[3]),  \
                   "r"(b0_), "r"(b1_))

__device__ __forceinline__ void split_bf16(float v, __nv_bfloat16& h, __nv_bfloat16& l) {
    h = __float2bfloat16(v);
    l = __float2bfloat16(v - __bfloat162float(h));
}

__device__ __forceinline__ float dinv_of(const float* deg, int node, int N) {
    if (node >= N) return 0.0f;
    float d = deg[node];
    return (d > 0.0f) ? rsqrtf(d) : 0.0f;
}

// ---------------------------------------------------------------------------
// Tensor-core GEMM with epilogue.
// X:[N,K] fp32 row-major, W:[K,NC] fp32 row-major.
// POST=false: O[n] = dinv[n] * (X@W)[n],  and S[n] = 0  (preps scatter target)
// POST=true : O[n] = relu(dinv[n]*S[n] + (X@W)[n] + b)
// Block: 128 rows, 128 threads (4 warps; warp = 32 rows x NC cols).
// ---------------------------------------------------------------------------
template <int K, int NC, bool POST>
__global__ void __launch_bounds__(128)
gemm_mma(const float* __restrict__ X, const float* __restrict__ W,
         const float* __restrict__ Bias, const float* __restrict__ deg,
         float* __restrict__ S, float* __restrict__ O, int N)
{
    constexpr int SA = K + 8;
    constexpr int NT = NC / 8;

    extern __shared__ __nv_bfloat16 sm[];
    __nv_bfloat16* Ah = sm;                 // [128][SA]
    __nv_bfloat16* Al = Ah + 128 * SA;
    __nv_bfloat16* Bh = Al + 128 * SA;      // [NC][SA] (W transposed, n-major)
    __nv_bfloat16* Bl = Bh + NC * SA;

    const int tid  = threadIdx.x;
    const int base = blockIdx.x * 128;

    // stage X tile (fp32 -> bf16 hi/lo)
    for (int idx = tid; idx < 128 * (K / 4); idx += 128) {
        int row = idx / (K / 4);
        int c4  = idx - row * (K / 4);
        int node = base + row;
        float4 v = (node < N) ? __ldg(reinterpret_cast<const float4*>(X + (size_t)node * K + c4 * 4))
                              : make_float4(0.f, 0.f, 0.f, 0.f);
        float vs[4] = {v.x, v.y, v.z, v.w};
        __nv_bfloat16 h[4], l[4];
#pragma unroll
        for (int j = 0; j < 4; j++) split_bf16(vs[j], h[j], l[j]);
        __nv_bfloat162* ph = reinterpret_cast<__nv_bfloat162*>(Ah + row * SA + c4 * 4);
        __nv_bfloat162* pl = reinterpret_cast<__nv_bfloat162*>(Al + row * SA + c4 * 4);
        ph[0] = __nv_bfloat162(h[0], h[1]); ph[1] = __nv_bfloat162(h[2], h[3]);
        pl[0] = __nv_bfloat162(l[0], l[1]); pl[1] = __nv_bfloat162(l[2], l[3]);
    }
    // stage W transposed
    for (int i = tid; i < K * NC; i += 128) {
        int k = i / NC, n = i - k * NC;
        __nv_bfloat16 h, l;
        split_bf16(W[i], h, l);
        Bh[n * SA + k] = h;
        Bl[n * SA + k] = l;
    }
    __syncthreads();

    const int warp = tid >> 5, lane = tid & 31;
    const int g = lane >> 2, t = lane & 3;

    float acc[2][NT][4];
#pragma unroll
    for (int mt = 0; mt < 2; mt++)
#pragma unroll
        for (int nt = 0; nt < NT; nt++)
#pragma unroll
            for (int j = 0; j < 4; j++) acc[mt][nt][j] = 0.0f;

#pragma unroll 2
    for (int ks = 0; ks < K; ks += 16) {
        const int k0 = ks + t * 2;
        uint32_t a[2][2][4];
#pragma unroll
        for (int mt = 0; mt < 2; mt++) {
            int r0 = warp * 32 + mt * 16 + g;
            a[mt][0][0] = *reinterpret_cast<const uint32_t*>(Ah + r0 * SA + k0);
            a[mt][0][1] = *reinterpret_cast<const uint32_t*>(Ah + (r0 + 8) * SA + k0);
            a[mt][0][2] = *reinterpret_cast<const uint32_t*>(Ah + r0 * SA + k0 + 8);
            a[mt][0][3] = *reinterpret_cast<const uint32_t*>(Ah + (r0 + 8) * SA + k0 + 8);
            a[mt][1][0] = *reinterpret_cast<const uint32_t*>(Al + r0 * SA + k0);
            a[mt][1][1] = *reinterpret_cast<const uint32_t*>(Al + (r0 + 8) * SA + k0);
            a[mt][1][2] = *reinterpret_cast<const uint32_t*>(Al + r0 * SA + k0 + 8);
            a[mt][1][3] = *reinterpret_cast<const uint32_t*>(Al + (r0 + 8) * SA + k0 + 8);
        }
#pragma unroll
        for (int nt = 0; nt < NT; nt++) {
            int n0 = nt * 8 + g;
            uint32_t bh0 = *reinterpret_cast<const uint32_t*>(Bh + n0 * SA + k0);
            uint32_t bh1 = *reinterpret_cast<const uint32_t*>(Bh + n0 * SA + k0 + 8);
            uint32_t bl0 = *reinterpret_cast<const uint32_t*>(Bl + n0 * SA + k0);
            uint32_t bl1 = *reinterpret_cast<const uint32_t*>(Bl + n0 * SA + k0 + 8);
#pragma unroll
            for (int mt = 0; mt < 2; mt++) {
                MMA_BF16(acc[mt][nt], a[mt][0], bh0, bh1);
                MMA_BF16(acc[mt][nt], a[mt][0], bl0, bl1);
                MMA_BF16(acc[mt][nt], a[mt][1], bh0, bh1);
            }
        }
    }

#pragma unroll
    for (int mt = 0; mt < 2; mt++) {
        int r0 = base + warp * 32 + mt * 16 + g;
        int r1 = r0 + 8;
        float dv0 = dinv_of(deg, r0, N);
        float dv1 = dinv_of(deg, r1, N);
#pragma unroll
        for (int nt = 0; nt < NT; nt++) {
            int col = nt * 8 + t * 2;
            const float* a4 = acc[mt][nt];
            if (POST) {
                float2 bb = *reinterpret_cast<const float2*>(Bias + col);
                if (r0 < N) {
                    float2 s = *reinterpret_cast<const float2*>(S + (size_t)r0 * NC + col);
                    float2 o;
                    o.x = fmaxf(fmaf(dv0, s.x, a4[0] + bb.x), 0.0f);
                    o.y = fmaxf(fmaf(dv0, s.y, a4[1] + bb.y), 0.0f);
                    *reinterpret_cast<float2*>(O + (size_t)r0 * NC + col) = o;
                }
                if (r1 < N) {
                    float2 s = *reinterpret_cast<const float2*>(S + (size_t)r1 * NC + col);
                    float2 o;
                    o.x = fmaxf(fmaf(dv1, s.x, a4[2] + bb.x), 0.0f);
                    o.y = fmaxf(fmaf(dv1, s.y, a4[3] + bb.y), 0.0f);
                    *reinterpret_cast<float2*>(O + (size_t)r1 * NC + col) = o;
                }
            } else {
                float2 z = make_float2(0.f, 0.f);
                if (r0 < N) {
                    *reinterpret_cast<float2*>(O + (size_t)r0 * NC + col) =
                        make_float2(a4[0] * dv0, a4[1] * dv0);
                    *reinterpret_cast<float2*>(S + (size_t)r0 * NC + col) = z;
                }
                if (r1 < N) {
                    *reinterpret_cast<float2*>(O + (size_t)r1 * NC + col) =
                        make_float2(a4[2] * dv1, a4[3] * dv1);
                    *reinterpret_cast<float2*>(S + (size_t)r1 * NC + col) = z;
                }
            }
        }
    }
}

// ---------------------------------------------------------------------------
// Edge scatter: S[col] += G[row]  (fire-and-forget 128-bit reduction)
// ---------------------------------------------------------------------------
template <int FQ>
__global__ void scatter_add(const int* __restrict__ rowi, const int* __restrict__ coli,
                            const float* __restrict__ G, float* __restrict__ S, int total)
{
    int idx = blockIdx.x * blockDim.x + threadIdx.x;
    if (idx >= total) return;
    int e = idx / FQ;
    int c = idx - e * FQ;
    int r  = __ldg(rowi + e);
    int cl = __ldg(coli + e);
    float4 v = __ldg(reinterpret_cast<const float4*>(G + ((size_t)r * FQ + c) * 4));
    float* p = S + ((size_t)cl * FQ + c) * 4;
    asm volatile("red.global.add.v4.f32 [%0], {%1,%2,%3,%4};"
                 :: "l"(p), "f"(v.x), "f"(v.y), "f"(v.z), "f"(v.w) : "memory");
}

// ---------------------------------------------------------------------------
extern "C" void kernel_launch(void* const* d_in, const int* in_sizes, int n_in,
                              void* d_out, int out_size)
{
    const float* x   = (const float*)d_in[0];
    const int*   ei  = (const int*)  d_in[1];
    const float* w1i = (const float*)d_in[2];
    const float* w1r = (const float*)d_in[3];
    const float* b1  = (const float*)d_in[4];
    const float* w2i = (const float*)d_in[5];
    const float* w2r = (const float*)d_in[6];
    const float* b2  = (const float*)d_in[7];
    float* out = (float*)d_out;

    const int E = in_sizes[1] / 2;
    const int N = out_size / 40;
    const int* row = ei;
    const int* col = ei + E;

    float *pdeg, *pA, *pS, *pG2;
    cudaGetSymbolAddress((void**)&pdeg, g_deg);
    cudaGetSymbolAddress((void**)&pA,   g_bufA);
    cudaGetSymbolAddress((void**)&pS,   g_bufS);
    cudaGetSymbolAddress((void**)&pG2,  g_bufG2);

    // degree (float counts; consumers compute rsqrt on the fly)
    cudaMemsetAsync(pdeg, 0, (size_t)N * sizeof(float));
    deg_kernel<<<(E + 255) / 256, 256>>>(col, pdeg, E);

    const int grid = (N + 127) / 128;

    // ---- Layer 1 (K=128, NC=64) ----
    const int smem1 = (2 * 128 + 2 * 64) * (128 + 8) * (int)sizeof(__nv_bfloat16);  // 104448
    cudaFuncSetAttribute(gemm_mma<128, 64, false>, cudaFuncAttributeMaxDynamicSharedMemorySize, smem1);
    cudaFuncSetAttribute(gemm_mma<128, 64, true>,  cudaFuncAttributeMaxDynamicSharedMemorySize, smem1);

    // g1 = dinv*(x@W1i) -> bufA ; S1 = 0
    gemm_mma<128, 64, false><<<grid, 128, smem1>>>(x, w1i, nullptr, pdeg, pS, pA, N);
    {   // S1[col] += g1[row]
        int total = E * 16;
        scatter_add<16><<<(total + 255) / 256, 256>>>(row, col, pA, pS, total);
    }
    // out1 = relu(dinv*S1 + x@W1r + b1) -> bufA (g1 dead)
    gemm_mma<128, 64, true><<<grid, 128, smem1>>>(x, w1r, b1, pdeg, pS, pA, N);

    // ---- Layer 2 (K=64, NC=40) ----
    const int smem2 = (2 * 128 + 2 * 40) * (64 + 8) * (int)sizeof(__nv_bfloat16);   // 48384
    float* pS2 = pS;   // S1 dead; reuse [0,40N)

    // g2 = dinv*(out1@W2i) -> bufG2 ; S2 = 0
    gemm_mma<64, 40, false><<<grid, 128, smem2>>>(pA, w2i, nullptr, pdeg, pS2, pG2, N);
    {   // S2[col] += g2[row]
        int total = E * 10;
        scatter_add<10><<<(total + 255) / 256, 256>>>(row, col, pG2, pS2, total);
    }
    // out = relu(dinv*S2 + out1@W2r + b2) -> d_out
    gemm_mma<64, 40, true><<<grid, 128, smem2>>>(pA, w2r, b2, pdeg, pS2, out, N);
}

// round 12
// speedup vs baseline: 1.6416x; 1.2406x over previous
#include <cuda_runtime.h>
#include <cuda_bf16.h>
#include <cstdint>

// ---------------------------------------------------------------------------
// BiARMA (2-layer ARMA GCN), N=100000, E=1e6, 128 -> 64 -> 40.
//
// deg[c] = #edges into c;  dinv = rsqrt(deg) (0 if deg==0), computed on the
// fly in the GEMM epilogues.
// g1   = dinv * (x @ W1i)            S1[c] += g1[row]  (fp32 vector atomics)
// out1 = relu(dinv*S1 + x @ W1r + b1)
// g2   = dinv * (out1 @ W2i)         S2[c] += g2[row]
// out  = relu(dinv*S2 + out1 @ W2r + b2)
//
// GEMMs: mma.sync.m16n8k16 bf16, 2-term split (Ah*Bh + Ah*Bl + Al*Bh).
// A fragments are loaded DIRECTLY from global into registers (A has no
// cross-thread reuse) and split in-register; only B (weights) lives in smem
// (~35 KB static) -> high occupancy (vs 104 KB smem / 11.6% occ before).
// Init GEMMs also zero the scatter target S (no memsets).
// Scatter: red.global.add.v4.f32 — measured at the REDG lane-issue floor.
//
// Scratch 67.6 MB: deg[N], bufA[64N] (g1 -> out1), bufS[64N] (S1; S2 in
// [0,40N)), bufG2[40N] (g2).
// ---------------------------------------------------------------------------

static constexpr int MAXN = 100000;

__device__ float g_deg  [MAXN];
__device__ float g_bufA [MAXN * 64];   // g1, later out1
__device__ float g_bufS [MAXN * 64];   // S1; later S2 in [0,40N)
__device__ float g_bufG2[MAXN * 40];   // g2

// ---------------------------------------------------------------------------
__global__ void deg_kernel(const int* __restrict__ col, float* __restrict__ deg, int E) {
    int i = blockIdx.x * blockDim.x + threadIdx.x;
    if (i < E) atomicAdd(&deg[col[i]], 1.0f);
}

// ---------------------------------------------------------------------------
#define MMA_BF16(c_, a_, b0_, b1_)                                          \
    asm volatile("mma.sync.aligned.m16n8k16.row.col.f32.bf16.bf16.f32 "     \
                 "{%0,%1,%2,%3}, {%4,%5,%6,%7}, {%8,%9}, {%0,%1,%2,%3};"    \
                 : "+f"((c_)[0]), "+f"((c_)[1]), "+f"((c_)[2]), "+f"((c_)[3]) \
                 : "r"((a_)[0]), "r"((a_)[1]), "r"((a_)[2]), "r"((a_)[3]),  \
                   "r"(b0_), "r"(b1_))

__device__ __forceinline__ void split_bf16(float v, __nv_bfloat16& h, __nv_bfloat16& l) {
    h = __float2bfloat16(v);
    l = __float2bfloat16(v - __bfloat162float(h));
}

// Split a float2 into packed bf16x2 hi + residual lo (2x cvt.rn.bf16x2).
__device__ __forceinline__ void cvt_split(float2 v, uint32_t& hi, uint32_t& lo) {
    uint32_t h;
    asm("cvt.rn.bf16x2.f32 %0, %1, %2;" : "=r"(h) : "f"(v.y), "f"(v.x));
    float hx = __uint_as_float(h << 16);            // exact bf16 -> f32
    float hy = __uint_as_float(h & 0xFFFF0000u);
    float rx = v.x - hx;
    float ry = v.y - hy;
    uint32_t l;
    asm("cvt.rn.bf16x2.f32 %0, %1, %2;" : "=r"(l) : "f"(ry), "f"(rx));
    hi = h; lo = l;
}

__device__ __forceinline__ float dinv_of(const float* deg, int node, int N) {
    if (node >= N) return 0.0f;
    float d = deg[node];
    return (d > 0.0f) ? rsqrtf(d) : 0.0f;
}

// ---------------------------------------------------------------------------
// Tensor-core GEMM, A direct-from-global, B in static smem.
// X:[N,K] fp32 row-major, W:[K,NC] fp32 row-major.
// POST=false: O[n] = dinv[n] * (X@W)[n],  and S[n] = 0  (preps scatter target)
// POST=true : O[n] = relu(dinv[n]*S[n] + (X@W)[n] + b)
// Block: 256 threads (8 warps), tile = 128 rows; warp owns 16 rows x NC cols.
// ---------------------------------------------------------------------------
template <int K, int NC, bool POST>
__global__ void __launch_bounds__(256)
gemm_mma(const float* __restrict__ X, const float* __restrict__ W,
         const float* __restrict__ Bias, const float* __restrict__ deg,
         float* __restrict__ S, float* __restrict__ O, int N)
{
    constexpr int SB = K + 8;          // padded k-stride (conflict-free frags)
    constexpr int NT = NC / 8;

    __shared__ __nv_bfloat16 Bh[NC * SB];
    __shared__ __nv_bfloat16 Bl[NC * SB];

    const int tid  = threadIdx.x;
    const int base = blockIdx.x * 128;

    // stage W transposed (n-major), split hi/lo
    for (int i = tid; i < K * NC; i += 256) {
        int k = i / NC, n = i - k * NC;
        __nv_bfloat16 h, l;
        split_bf16(W[i], h, l);
        Bh[n * SB + k] = h;
        Bl[n * SB + k] = l;
    }
    __syncthreads();

    const int warp = tid >> 5, lane = tid & 31;
    const int g = lane >> 2, t = lane & 3;

    const int r0 = base + warp * 16 + g;     // rows r0 and r0+8
    const int r1 = r0 + 8;
    const bool ok0 = r0 < N, ok1 = r1 < N;
    const float* X0 = X + (size_t)r0 * K;
    const float* X1 = X + (size_t)r1 * K;

    float acc[NT][4];
#pragma unroll
    for (int nt = 0; nt < NT; nt++)
#pragma unroll
        for (int j = 0; j < 4; j++) acc[nt][j] = 0.0f;

#pragma unroll
    for (int ks = 0; ks < K; ks += 16) {
        const int k0 = ks + t * 2;
        // A fragments straight from global (predicated on row validity)
        float2 v0 = ok0 ? __ldg(reinterpret_cast<const float2*>(X0 + k0))     : make_float2(0.f, 0.f);
        float2 v1 = ok1 ? __ldg(reinterpret_cast<const float2*>(X1 + k0))     : make_float2(0.f, 0.f);
        float2 v2 = ok0 ? __ldg(reinterpret_cast<const float2*>(X0 + k0 + 8)) : make_float2(0.f, 0.f);
        float2 v3 = ok1 ? __ldg(reinterpret_cast<const float2*>(X1 + k0 + 8)) : make_float2(0.f, 0.f);

        uint32_t ah[4], al[4];
        cvt_split(v0, ah[0], al[0]);
        cvt_split(v1, ah[1], al[1]);
        cvt_split(v2, ah[2], al[2]);
        cvt_split(v3, ah[3], al[3]);

#pragma unroll
        for (int nt = 0; nt < NT; nt++) {
            int n0 = nt * 8 + g;
            uint32_t bh0 = *reinterpret_cast<const uint32_t*>(Bh + n0 * SB + k0);
            uint32_t bh1 = *reinterpret_cast<const uint32_t*>(Bh + n0 * SB + k0 + 8);
            uint32_t bl0 = *reinterpret_cast<const uint32_t*>(Bl + n0 * SB + k0);
            uint32_t bl1 = *reinterpret_cast<const uint32_t*>(Bl + n0 * SB + k0 + 8);
            MMA_BF16(acc[nt], ah, bh0, bh1);
            MMA_BF16(acc[nt], ah, bl0, bl1);
            MMA_BF16(acc[nt], al, bh0, bh1);
        }
    }

    // ---- epilogue ----
    const float dv0 = dinv_of(deg, r0, N);
    const float dv1 = dinv_of(deg, r1, N);
#pragma unroll
    for (int nt = 0; nt < NT; nt++) {
        int col = nt * 8 + t * 2;
        const float* a4 = acc[nt];
        if (POST) {
            float2 bb = *reinterpret_cast<const float2*>(Bias + col);
            if (ok0) {
                float2 s = *reinterpret_cast<const float2*>(S + (size_t)r0 * NC + col);
                float2 o;
                o.x = fmaxf(fmaf(dv0, s.x, a4[0] + bb.x), 0.0f);
                o.y = fmaxf(fmaf(dv0, s.y, a4[1] + bb.y), 0.0f);
                *reinterpret_cast<float2*>(O + (size_t)r0 * NC + col) = o;
            }
            if (ok1) {
                float2 s = *reinterpret_cast<const float2*>(S + (size_t)r1 * NC + col);
                float2 o;
                o.x = fmaxf(fmaf(dv1, s.x, a4[2] + bb.x), 0.0f);
                o.y = fmaxf(fmaf(dv1, s.y, a4[3] + bb.y), 0.0f);
                *reinterpret_cast<float2*>(O + (size_t)r1 * NC + col) = o;
            }
        } else {
            float2 z = make_float2(0.f, 0.f);
            if (ok0) {
                *reinterpret_cast<float2*>(O + (size_t)r0 * NC + col) =
                    make_float2(a4[0] * dv0, a4[1] * dv0);
                *reinterpret_cast<float2*>(S + (size_t)r0 * NC + col) = z;
            }
            if (ok1) {
                *reinterpret_cast<float2*>(O + (size_t)r1 * NC + col) =
                    make_float2(a4[2] * dv1, a4[3] * dv1);
                *reinterpret_cast<float2*>(S + (size_t)r1 * NC + col) = z;
            }
        }
    }
}

// ---------------------------------------------------------------------------
// Edge scatter: S[col] += G[row]  (fire-and-forget 128-bit reduction)
// ---------------------------------------------------------------------------
template <int FQ>
__global__ void scatter_add(const int* __restrict__ rowi, const int* __restrict__ coli,
                            const float* __restrict__ G, float* __restrict__ S, int total)
{
    int idx = blockIdx.x * blockDim.x + threadIdx.x;
    if (idx >= total) return;
    int e = idx / FQ;
    int c = idx - e * FQ;
    int r  = __ldg(rowi + e);
    int cl = __ldg(coli + e);
    float4 v = __ldg(reinterpret_cast<const float4*>(G + ((size_t)r * FQ + c) * 4));
    float* p = S + ((size_t)cl * FQ + c) * 4;
    asm volatile("red.global.add.v4.f32 [%0], {%1,%2,%3,%4};"
                 :: "l"(p), "f"(v.x), "f"(v.y), "f"(v.z), "f"(v.w) : "memory");
}

// ---------------------------------------------------------------------------
extern "C" void kernel_launch(void* const* d_in, const int* in_sizes, int n_in,
                              void* d_out, int out_size)
{
    const float* x   = (const float*)d_in[0];
    const int*   ei  = (const int*)  d_in[1];
    const float* w1i = (const float*)d_in[2];
    const float* w1r = (const float*)d_in[3];
    const float* b1  = (const float*)d_in[4];
    const float* w2i = (const float*)d_in[5];
    const float* w2r = (const float*)d_in[6];
    const float* b2  = (const float*)d_in[7];
    float* out = (float*)d_out;

    const int E = in_sizes[1] / 2;
    const int N = out_size / 40;
    const int* row = ei;
    const int* col = ei + E;

    float *pdeg, *pA, *pS, *pG2;
    cudaGetSymbolAddress((void**)&pdeg, g_deg);
    cudaGetSymbolAddress((void**)&pA,   g_bufA);
    cudaGetSymbolAddress((void**)&pS,   g_bufS);
    cudaGetSymbolAddress((void**)&pG2,  g_bufG2);

    // degree (float counts; consumers compute rsqrt on the fly)
    cudaMemsetAsync(pdeg, 0, (size_t)N * sizeof(float));
    deg_kernel<<<(E + 255) / 256, 256>>>(col, pdeg, E);

    const int grid = (N + 127) / 128;

    // ---- Layer 1 (K=128, NC=64) ----
    // g1 = dinv*(x@W1i) -> bufA ; S1 = 0
    gemm_mma<128, 64, false><<<grid, 256>>>(x, w1i, nullptr, pdeg, pS, pA, N);
    {   // S1[col] += g1[row]
        int total = E * 16;
        scatter_add<16><<<(total + 255) / 256, 256>>>(row, col, pA, pS, total);
    }
    // out1 = relu(dinv*S1 + x@W1r + b1) -> bufA (g1 dead)
    gemm_mma<128, 64, true><<<grid, 256>>>(x, w1r, b1, pdeg, pS, pA, N);

    // ---- Layer 2 (K=64, NC=40) ----
    float* pS2 = pS;   // S1 dead; reuse [0,40N)

    // g2 = dinv*(out1@W2i) -> bufG2 ; S2 = 0
    gemm_mma<64, 40, false><<<grid, 256>>>(pA, w2i, nullptr, pdeg, pS2, pG2, N);
    {   // S2[col] += g2[row]
        int total = E * 10;
        scatter_add<10><<<(total + 255) / 256, 256>>>(row, col, pG2, pS2, total);
    }
    // out = relu(dinv*S2 + out1@W2r + b2) -> d_out
    gemm_mma<64, 40, true><<<grid, 256>>>(pA, w2r, b2, pdeg, pS2, out, N);
}

// round 13
// speedup vs baseline: 1.8557x; 1.1304x over previous
#include <cuda_runtime.h>
#include <cuda_bf16.h>
#include <cstdint>

// ---------------------------------------------------------------------------
// BiARMA (2-layer ARMA GCN), N=100000, E=1e6, 128 -> 64 -> 40.
//
// deg[c] = #edges into c;  dinv = rsqrt(deg) (0 if deg==0), on the fly.
// g1   = dinv * (x @ W1i)            S1[c] += g1[row]  (fp32 vector atomics)
// R1   = x @ W1r + b1                      (FORKED stream: overlaps scatter1)
// out1 = relu(dinv*S1 + R1)
// g2   = dinv * (out1 @ W2i)         S2[c] += g2[row]
// R2   = out1 @ W2r + b2                   (FORKED stream: overlaps scatter2)
// out  = relu(dinv*S2 + R2)
//
// GEMMs: mma.sync.m16n8k16 bf16, 2-term split (Ah*Bh + Ah*Bl + Al*Bh);
// A direct-from-global (no cross-thread reuse), B in static smem.
// Scatter: red.global.add.v4.f32 — at the REDG lane-issue floor; the root
// GEMMs are moved OFF the critical path to overlap it (cross-stream capture).
//
// Arena 77.2 MB: deg[N] + arena[192N]:
//   [0,64N)     R1        -> layer2: g2 [0,40N), S2 [40N,80N)
//   [64N,128N)  S1        -> layer2: R2 [80N,120N)
//   [128N,192N) g1 -> out1
// ---------------------------------------------------------------------------

static constexpr int MAXN = 100000;

__device__ float g_deg  [MAXN];
__device__ float g_arena[(size_t)MAXN * 192];

// ---------------------------------------------------------------------------
__global__ void deg_kernel(const int* __restrict__ col, float* __restrict__ deg, int E) {
    int i = blockIdx.x * blockDim.x + threadIdx.x;
    if (i < E) atomicAdd(&deg[col[i]], 1.0f);
}

// ---------------------------------------------------------------------------
#define MMA_BF16(c_, a_, b0_, b1_)                                          \
    asm volatile("mma.sync.aligned.m16n8k16.row.col.f32.bf16.bf16.f32 "     \
                 "{%0,%1,%2,%3}, {%4,%5,%6,%7}, {%8,%9}, {%0,%1,%2,%3};"    \
                 : "+f"((c_)[0]), "+f"((c_)[1]), "+f"((c_)[2]), "+f"((c_)[3]) \
                 : "r"((a_)[0]), "r"((a_)[1]), "r"((a_)[2]), "r"((a_)[3]),  \
                   "r"(b0_), "r"(b1_))

__device__ __forceinline__ void split_bf16(float v, __nv_bfloat16& h, __nv_bfloat16& l) {
    h = __float2bfloat16(v);
    l = __float2bfloat16(v - __bfloat162float(h));
}

// Split a float2 into packed bf16x2 hi + residual lo.
__device__ __forceinline__ void cvt_split(float2 v, uint32_t& hi, uint32_t& lo) {
    uint32_t h;
    asm("cvt.rn.bf16x2.f32 %0, %1, %2;" : "=r"(h) : "f"(v.y), "f"(v.x));
    float hx = __uint_as_float(h << 16);
    float hy = __uint_as_float(h & 0xFFFF0000u);
    float rx = v.x - hx;
    float ry = v.y - hy;
    uint32_t l;
    asm("cvt.rn.bf16x2.f32 %0, %1, %2;" : "=r"(l) : "f"(ry), "f"(rx));
    hi = h; lo = l;
}

__device__ __forceinline__ float dinv_of(const float* deg, int node, int N) {
    if (node >= N) return 0.0f;
    float d = deg[node];
    return (d > 0.0f) ? rsqrtf(d) : 0.0f;
}

// ---------------------------------------------------------------------------
// Tensor-core GEMM, A direct-from-global, B in static smem.
// ROOT=false (INIT): O[n] = dinv[n]*(X@W)[n]  and  S[n] = 0
// ROOT=true        : O[n] = (X@W)[n] + bias
// Block: 256 threads (8 warps), tile = 128 rows; warp owns 16 rows x NC cols.
// ---------------------------------------------------------------------------
template <int K, int NC, bool ROOT>
__global__ void __launch_bounds__(256)
gemm_mma(const float* __restrict__ X, const float* __restrict__ W,
         const float* __restrict__ Bias, const float* __restrict__ deg,
         float* __restrict__ S, float* __restrict__ O, int N)
{
    constexpr int SB = K + 8;
    constexpr int NT = NC / 8;

    __shared__ __nv_bfloat16 Bh[NC * SB];
    __shared__ __nv_bfloat16 Bl[NC * SB];

    const int tid  = threadIdx.x;
    const int base = blockIdx.x * 128;

    for (int i = tid; i < K * NC; i += 256) {
        int k = i / NC, n = i - k * NC;
        __nv_bfloat16 h, l;
        split_bf16(W[i], h, l);
        Bh[n * SB + k] = h;
        Bl[n * SB + k] = l;
    }
    __syncthreads();

    const int warp = tid >> 5, lane = tid & 31;
    const int g = lane >> 2, t = lane & 3;

    const int r0 = base + warp * 16 + g;
    const int r1 = r0 + 8;
    const bool ok0 = r0 < N, ok1 = r1 < N;
    const float* X0 = X + (size_t)r0 * K;
    const float* X1 = X + (size_t)r1 * K;

    float acc[NT][4];
#pragma unroll
    for (int nt = 0; nt < NT; nt++)
#pragma unroll
        for (int j = 0; j < 4; j++) acc[nt][j] = 0.0f;

#pragma unroll
    for (int ks = 0; ks < K; ks += 16) {
        const int k0 = ks + t * 2;
        float2 v0 = ok0 ? __ldg(reinterpret_cast<const float2*>(X0 + k0))     : make_float2(0.f, 0.f);
        float2 v1 = ok1 ? __ldg(reinterpret_cast<const float2*>(X1 + k0))     : make_float2(0.f, 0.f);
        float2 v2 = ok0 ? __ldg(reinterpret_cast<const float2*>(X0 + k0 + 8)) : make_float2(0.f, 0.f);
        float2 v3 = ok1 ? __ldg(reinterpret_cast<const float2*>(X1 + k0 + 8)) : make_float2(0.f, 0.f);

        uint32_t ah[4], al[4];
        cvt_split(v0, ah[0], al[0]);
        cvt_split(v1, ah[1], al[1]);
        cvt_split(v2, ah[2], al[2]);
        cvt_split(v3, ah[3], al[3]);

#pragma unroll
        for (int nt = 0; nt < NT; nt++) {
            int n0 = nt * 8 + g;
            uint32_t bh0 = *reinterpret_cast<const uint32_t*>(Bh + n0 * SB + k0);
            uint32_t bh1 = *reinterpret_cast<const uint32_t*>(Bh + n0 * SB + k0 + 8);
            uint32_t bl0 = *reinterpret_cast<const uint32_t*>(Bl + n0 * SB + k0);
            uint32_t bl1 = *reinterpret_cast<const uint32_t*>(Bl + n0 * SB + k0 + 8);
            MMA_BF16(acc[nt], ah, bh0, bh1);
            MMA_BF16(acc[nt], ah, bl0, bl1);
            MMA_BF16(acc[nt], al, bh0, bh1);
        }
    }

    // ---- epilogue ----
    const float dv0 = ROOT ? 0.0f : dinv_of(deg, r0, N);
    const float dv1 = ROOT ? 0.0f : dinv_of(deg, r1, N);
#pragma unroll
    for (int nt = 0; nt < NT; nt++) {
        int col = nt * 8 + t * 2;
        const float* a4 = acc[nt];
        if (ROOT) {
            float2 bb = *reinterpret_cast<const float2*>(Bias + col);
            if (ok0)
                *reinterpret_cast<float2*>(O + (size_t)r0 * NC + col) =
                    make_float2(a4[0] + bb.x, a4[1] + bb.y);
            if (ok1)
                *reinterpret_cast<float2*>(O + (size_t)r1 * NC + col) =
                    make_float2(a4[2] + bb.x, a4[3] + bb.y);
        } else {
            float2 z = make_float2(0.f, 0.f);
            if (ok0) {
                *reinterpret_cast<float2*>(O + (size_t)r0 * NC + col) =
                    make_float2(a4[0] * dv0, a4[1] * dv0);
                *reinterpret_cast<float2*>(S + (size_t)r0 * NC + col) = z;
            }
            if (ok1) {
                *reinterpret_cast<float2*>(O + (size_t)r1 * NC + col) =
                    make_float2(a4[2] * dv1, a4[3] * dv1);
                *reinterpret_cast<float2*>(S + (size_t)r1 * NC + col) = z;
            }
        }
    }
}

// ---------------------------------------------------------------------------
// Edge scatter: S[col] += G[row]  (fire-and-forget 128-bit reduction)
// ---------------------------------------------------------------------------
template <int FQ>
__global__ void scatter_add(const int* __restrict__ rowi, const int* __restrict__ coli,
                            const float* __restrict__ G, float* __restrict__ S, int total)
{
    int idx = blockIdx.x * blockDim.x + threadIdx.x;
    if (idx >= total) return;
    int e = idx / FQ;
    int c = idx - e * FQ;
    int r  = __ldg(rowi + e);
    int cl = __ldg(coli + e);
    float4 v = __ldg(reinterpret_cast<const float4*>(G + ((size_t)r * FQ + c) * 4));
    float* p = S + ((size_t)cl * FQ + c) * 4;
    asm volatile("red.global.add.v4.f32 [%0], {%1,%2,%3,%4};"
                 :: "l"(p), "f"(v.x), "f"(v.y), "f"(v.z), "f"(v.w) : "memory");
}

// ---------------------------------------------------------------------------
// Elementwise post: O = relu(dinv[node]*S + R)   (float4 lanes)
// ---------------------------------------------------------------------------
template <int FQ>
__global__ void post_kernel(const float* __restrict__ S, const float* __restrict__ R,
                            const float* __restrict__ deg, float* __restrict__ O,
                            int total4, int N)
{
    int idx = blockIdx.x * blockDim.x + threadIdx.x;
    if (idx >= total4) return;
    int node = idx / FQ;
    float dv = dinv_of(deg, node, N);
    float4 s = *reinterpret_cast<const float4*>(S + (size_t)idx * 4);
    float4 r = *reinterpret_cast<const float4*>(R + (size_t)idx * 4);
    float4 o;
    o.x = fmaxf(fmaf(dv, s.x, r.x), 0.0f);
    o.y = fmaxf(fmaf(dv, s.y, r.y), 0.0f);
    o.z = fmaxf(fmaf(dv, s.z, r.z), 0.0f);
    o.w = fmaxf(fmaf(dv, s.w, r.w), 0.0f);
    *reinterpret_cast<float4*>(O + (size_t)idx * 4) = o;
}

// ---------------------------------------------------------------------------
extern "C" void kernel_launch(void* const* d_in, const int* in_sizes, int n_in,
                              void* d_out, int out_size)
{
    const float* x   = (const float*)d_in[0];
    const int*   ei  = (const int*)  d_in[1];
    const float* w1i = (const float*)d_in[2];
    const float* w1r = (const float*)d_in[3];
    const float* b1  = (const float*)d_in[4];
    const float* w2i = (const float*)d_in[5];
    const float* w2r = (const float*)d_in[6];
    const float* b2  = (const float*)d_in[7];
    float* out = (float*)d_out;

    const int E = in_sizes[1] / 2;
    const int N = out_size / 40;
    const int* row = ei;
    const int* col = ei + E;

    float *pdeg, *arena;
    cudaGetSymbolAddress((void**)&pdeg,  g_deg);
    cudaGetSymbolAddress((void**)&arena, g_arena);

    // Arena layout
    float* pR1   = arena;                       // [0,64N)
    float* pS1   = arena + (size_t)N * 64;      // [64N,128N)
    float* pA    = arena + (size_t)N * 128;     // [128N,192N): g1 -> out1
    float* pG2   = arena;                       // layer2: [0,40N)    (R1 dead)
    float* pS2   = arena + (size_t)N * 40;      // layer2: [40N,80N)
    float* pR2   = arena + (size_t)N * 80;      // layer2: [80N,120N) (S1 dead)

    // Side stream + events (created once, outside any capture).
    static cudaStream_t s2 = nullptr;
    static cudaEvent_t evA = nullptr, evB = nullptr, evC = nullptr, evD = nullptr;
    if (s2 == nullptr) {
        cudaStreamCreateWithFlags(&s2, cudaStreamNonBlocking);
        cudaEventCreateWithFlags(&evA, cudaEventDisableTiming);
        cudaEventCreateWithFlags(&evB, cudaEventDisableTiming);
        cudaEventCreateWithFlags(&evC, cudaEventDisableTiming);
        cudaEventCreateWithFlags(&evD, cudaEventDisableTiming);
    }

    const int grid = (N + 127) / 128;

    // ---- fork: R1 = x@W1r + b1 on side stream (overlaps deg/gemm1i/scatter1)
    cudaEventRecord(evA, 0);
    cudaStreamWaitEvent(s2, evA, 0);
    gemm_mma<128, 64, true><<<grid, 256, 0, s2>>>(x, w1r, b1, nullptr, nullptr, pR1, N);
    cudaEventRecord(evB, s2);

    // ---- main stream: deg, init GEMM, scatter ----
    cudaMemsetAsync(pdeg, 0, (size_t)N * sizeof(float));
    deg_kernel<<<(E + 255) / 256, 256>>>(col, pdeg, E);

    // g1 = dinv*(x@W1i) -> pA ; S1 = 0
    gemm_mma<128, 64, false><<<grid, 256>>>(x, w1i, nullptr, pdeg, pS1, pA, N);
    {   // S1[col] += g1[row]
        int total = E * 16;
        scatter_add<16><<<(total + 255) / 256, 256>>>(row, col, pA, pS1, total);
    }

    // ---- join; out1 = relu(dinv*S1 + R1) -> pA (over g1) ----
    cudaStreamWaitEvent(0, evB, 0);
    {
        int total4 = N * 16;
        post_kernel<16><<<(total4 + 255) / 256, 256>>>(pS1, pR1, pdeg, pA, total4, N);
    }

    // ---- fork: R2 = out1@W2r + b2 on side stream (overlaps gemm2i/scatter2)
    cudaEventRecord(evC, 0);
    cudaStreamWaitEvent(s2, evC, 0);
    gemm_mma<64, 40, true><<<grid, 256, 0, s2>>>(pA, w2r, b2, nullptr, nullptr, pR2, N);
    cudaEventRecord(evD, s2);

    // ---- main stream: init GEMM 2, scatter 2 ----
    // g2 = dinv*(out1@W2i) -> pG2 ; S2 = 0
    gemm_mma<64, 40, false><<<grid, 256>>>(pA, w2i, nullptr, pdeg, pS2, pG2, N);
    {   // S2[col] += g2[row]
        int total = E * 10;
        scatter_add<10><<<(total + 255) / 256, 256>>>(row, col, pG2, pS2, total);
    }

    // ---- join; out = relu(dinv*S2 + R2) -> d_out ----
    cudaStreamWaitEvent(0, evD, 0);
    {
        int total4 = N * 10;
        post_kernel<10><<<(total4 + 255) / 256, 256>>>(pS2, pR2, pdeg, out, total4, N);
    }
}

// round 15
// speedup vs baseline: 1.8898x; 1.0184x over previous
#include <cuda_runtime.h>
#include <cuda_bf16.h>
#include <cstdint>

// ---------------------------------------------------------------------------
// BiARMA (2-layer ARMA GCN), N=100000, E=1e6, 128 -> 64 -> 40.
//
// deg[c] = #edges into c;  dinv = rsqrt(deg) (0 if deg==0), on the fly.
// g1   = dinv * (x @ W1i)            S1[c] += g1[row]  (fp32 vector atomics)
// R1   = x @ W1r + b1                      (side stream, overlaps scatter1)
// out1 = relu(dinv*S1 + R1)                (NOT materialized: fused into the
//                                           A-loads of both layer-2 GEMMs)
// g2   = dinv * (out1 @ W2i)         S2[c] += g2[row]
// R2   = out1 @ W2r + b2 -> d_out          (side stream, overlaps scatter2)
// out  = relu(dinv*S2 + R2)                (in place over d_out)
//
// GEMMs: mma.sync.m16n8k16 bf16, 2-term split (Ah*Bh + Ah*Bl + Al*Bh);
// A direct-from-global (optionally fused relu(dinv*S+R)), B in static smem.
// Scatter: red.global.add.v4.f32 — at the REDG lane-issue floor; root GEMMs
// overlap it on a forked stream (cross-stream graph capture).
//
// Arena 83.6 MB, NO ALIASING between concurrently-live regions:
//   R1 [0,64N)      (read by gemm2i/gemm2r; never overwritten while live)
//   S1 [64N,128N)   (read by gemm2i/gemm2r)
//   g1 [128N,192N)  (dead after scatter1; g2 reuses [128N,168N))
//   S2 [168N,208N)  (fresh region)
//   R2 -> d_out
// ---------------------------------------------------------------------------

static constexpr int MAXN = 100000;

__device__ float g_deg  [MAXN];
__device__ float g_arena[(size_t)MAXN * 208];

// ---------------------------------------------------------------------------
__global__ void deg_kernel(const int* __restrict__ col, float* __restrict__ deg, int E) {
    int i = blockIdx.x * blockDim.x + threadIdx.x;
    if (i < E) atomicAdd(&deg[col[i]], 1.0f);
}

// ---------------------------------------------------------------------------
#define MMA_BF16(c_, a_, b0_, b1_)                                          \
    asm volatile("mma.sync.aligned.m16n8k16.row.col.f32.bf16.bf16.f32 "     \
                 "{%0,%1,%2,%3}, {%4,%5,%6,%7}, {%8,%9}, {%0,%1,%2,%3};"    \
                 : "+f"((c_)[0]), "+f"((c_)[1]), "+f"((c_)[2]), "+f"((c_)[3]) \
                 : "r"((a_)[0]), "r"((a_)[1]), "r"((a_)[2]), "r"((a_)[3]),  \
                   "r"(b0_), "r"(b1_))

__device__ __forceinline__ void split_bf16(float v, __nv_bfloat16& h, __nv_bfloat16& l) {
    h = __float2bfloat16(v);
    l = __float2bfloat16(v - __bfloat162float(h));
}

// Split a float2 into packed bf16x2 hi + residual lo.
__device__ __forceinline__ void cvt_split(float2 v, uint32_t& hi, uint32_t& lo) {
    uint32_t h;
    asm("cvt.rn.bf16x2.f32 %0, %1, %2;" : "=r"(h) : "f"(v.y), "f"(v.x));
    float hx = __uint_as_float(h << 16);
    float hy = __uint_as_float(h & 0xFFFF0000u);
    float rx = v.x - hx;
    float ry = v.y - hy;
    uint32_t l;
    asm("cvt.rn.bf16x2.f32 %0, %1, %2;" : "=r"(l) : "f"(ry), "f"(rx));
    hi = h; lo = l;
}

__device__ __forceinline__ float dinv_of(const float* deg, int node, int N) {
    if (node >= N) return 0.0f;
    float d = deg[node];
    return (d > 0.0f) ? rsqrtf(d) : 0.0f;
}

// ---------------------------------------------------------------------------
// Tensor-core GEMM, A direct-from-global, B in static smem.
// FUSEA=false: A[n,k] = X[n,k]
// FUSEA=true : A[n,k] = relu(dinv[n]*SA[n,k] + RA[n,k])   (out1 on the fly)
// ROOT=false (INIT): O[n] = dinv[n]*(A@W)[n]  and  S[n] = 0
// ROOT=true        : O[n] = (A@W)[n] + bias
// Block: 256 threads (8 warps), tile = 128 rows; warp owns 16 rows x NC cols.
// ---------------------------------------------------------------------------
template <int K, int NC, bool ROOT, bool FUSEA>
__global__ void __launch_bounds__(256)
gemm_mma(const float* __restrict__ X,
         const float* __restrict__ SA, const float* __restrict__ RA,
         const float* __restrict__ W,  const float* __restrict__ Bias,
         const float* __restrict__ deg,
         float* __restrict__ S, float* __restrict__ O, int N)
{
    constexpr int SB = K + 8;
    constexpr int NT = NC / 8;

    __shared__ __nv_bfloat16 Bh[NC * SB];
    __shared__ __nv_bfloat16 Bl[NC * SB];

    const int tid  = threadIdx.x;
    const int base = blockIdx.x * 128;

    for (int i = tid; i < K * NC; i += 256) {
        int k = i / NC, n = i - k * NC;
        __nv_bfloat16 h, l;
        split_bf16(W[i], h, l);
        Bh[n * SB + k] = h;
        Bl[n * SB + k] = l;
    }
    __syncthreads();

    const int warp = tid >> 5, lane = tid & 31;
    const int g = lane >> 2, t = lane & 3;

    const int r0 = base + warp * 16 + g;
    const int r1 = r0 + 8;
    const bool ok0 = r0 < N, ok1 = r1 < N;

    // dinv for the two A rows (needed for FUSEA A-gen and for INIT epilogue)
    const float dv0 = (FUSEA || !ROOT) ? dinv_of(deg, r0, N) : 0.0f;
    const float dv1 = (FUSEA || !ROOT) ? dinv_of(deg, r1, N) : 0.0f;

    const float* X0  = FUSEA ? nullptr : X + (size_t)r0 * K;
    const float* X1  = FUSEA ? nullptr : X + (size_t)r1 * K;
    const float* S0  = FUSEA ? SA + (size_t)r0 * K : nullptr;
    const float* S1p = FUSEA ? SA + (size_t)r1 * K : nullptr;
    const float* R0  = FUSEA ? RA + (size_t)r0 * K : nullptr;
    const float* R1p = FUSEA ? RA + (size_t)r1 * K : nullptr;

    float acc[NT][4];
#pragma unroll
    for (int nt = 0; nt < NT; nt++)
#pragma unroll
        for (int j = 0; j < 4; j++) acc[nt][j] = 0.0f;

#pragma unroll
    for (int ks = 0; ks < K; ks += 16) {
        const int k0 = ks + t * 2;

        float2 v0, v1, v2, v3;
        if (FUSEA) {
            float2 z = make_float2(0.f, 0.f);
            float2 s0 = ok0 ? __ldg(reinterpret_cast<const float2*>(S0 + k0))     : z;
            float2 s1 = ok1 ? __ldg(reinterpret_cast<const float2*>(S1p + k0))    : z;
            float2 s2 = ok0 ? __ldg(reinterpret_cast<const float2*>(S0 + k0 + 8)) : z;
            float2 s3 = ok1 ? __ldg(reinterpret_cast<const float2*>(S1p + k0 + 8)): z;
            float2 q0 = ok0 ? __ldg(reinterpret_cast<const float2*>(R0 + k0))     : z;
            float2 q1 = ok1 ? __ldg(reinterpret_cast<const float2*>(R1p + k0))    : z;
            float2 q2 = ok0 ? __ldg(reinterpret_cast<const float2*>(R0 + k0 + 8)) : z;
            float2 q3 = ok1 ? __ldg(reinterpret_cast<const float2*>(R1p + k0 + 8)): z;
            v0.x = fmaxf(fmaf(dv0, s0.x, q0.x), 0.0f);
            v0.y = fmaxf(fmaf(dv0, s0.y, q0.y), 0.0f);
            v1.x = fmaxf(fmaf(dv1, s1.x, q1.x), 0.0f);
            v1.y = fmaxf(fmaf(dv1, s1.y, q1.y), 0.0f);
            v2.x = fmaxf(fmaf(dv0, s2.x, q2.x), 0.0f);
            v2.y = fmaxf(fmaf(dv0, s2.y, q2.y), 0.0f);
            v3.x = fmaxf(fmaf(dv1, s3.x, q3.x), 0.0f);
            v3.y = fmaxf(fmaf(dv1, s3.y, q3.y), 0.0f);
        } else {
            float2 z = make_float2(0.f, 0.f);
            v0 = ok0 ? __ldg(reinterpret_cast<const float2*>(X0 + k0))     : z;
            v1 = ok1 ? __ldg(reinterpret_cast<const float2*>(X1 + k0))     : z;
            v2 = ok0 ? __ldg(reinterpret_cast<const float2*>(X0 + k0 + 8)) : z;
            v3 = ok1 ? __ldg(reinterpret_cast<const float2*>(X1 + k0 + 8)) : z;
        }

        uint32_t ah[4], al[4];
        cvt_split(v0, ah[0], al[0]);
        cvt_split(v1, ah[1], al[1]);
        cvt_split(v2, ah[2], al[2]);
        cvt_split(v3, ah[3], al[3]);

#pragma unroll
        for (int nt = 0; nt < NT; nt++) {
            int n0 = nt * 8 + g;
            uint32_t bh0 = *reinterpret_cast<const uint32_t*>(Bh + n0 * SB + k0);
            uint32_t bh1 = *reinterpret_cast<const uint32_t*>(Bh + n0 * SB + k0 + 8);
            uint32_t bl0 = *reinterpret_cast<const uint32_t*>(Bl + n0 * SB + k0);
            uint32_t bl1 = *reinterpret_cast<const uint32_t*>(Bl + n0 * SB + k0 + 8);
            MMA_BF16(acc[nt], ah, bh0, bh1);
            MMA_BF16(acc[nt], ah, bl0, bl1);
            MMA_BF16(acc[nt], al, bh0, bh1);
        }
    }

    // ---- epilogue ----
#pragma unroll
    for (int nt = 0; nt < NT; nt++) {
        int col = nt * 8 + t * 2;
        const float* a4 = acc[nt];
        if (ROOT) {
            float2 bb = *reinterpret_cast<const float2*>(Bias + col);
            if (ok0)
                *reinterpret_cast<float2*>(O + (size_t)r0 * NC + col) =
                    make_float2(a4[0] + bb.x, a4[1] + bb.y);
            if (ok1)
                *reinterpret_cast<float2*>(O + (size_t)r1 * NC + col) =
                    make_float2(a4[2] + bb.x, a4[3] + bb.y);
        } else {
            float2 z = make_float2(0.f, 0.f);
            if (ok0) {
                *reinterpret_cast<float2*>(O + (size_t)r0 * NC + col) =
                    make_float2(a4[0] * dv0, a4[1] * dv0);
                *reinterpret_cast<float2*>(S + (size_t)r0 * NC + col) = z;
            }
            if (ok1) {
                *reinterpret_cast<float2*>(O + (size_t)r1 * NC + col) =
                    make_float2(a4[2] * dv1, a4[3] * dv1);
                *reinterpret_cast<float2*>(S + (size_t)r1 * NC + col) = z;
            }
        }
    }
}

// ---------------------------------------------------------------------------
// Edge scatter: S[col] += G[row]  (fire-and-forget 128-bit reduction)
// ---------------------------------------------------------------------------
template <int FQ>
__global__ void scatter_add(const int* __restrict__ rowi, const int* __restrict__ coli,
                            const float* __restrict__ G, float* __restrict__ S, int total)
{
    int idx = blockIdx.x * blockDim.x + threadIdx.x;
    if (idx >= total) return;
    int e = idx / FQ;
    int c = idx - e * FQ;
    int r  = __ldg(rowi + e);
    int cl = __ldg(coli + e);
    float4 v = __ldg(reinterpret_cast<const float4*>(G + ((size_t)r * FQ + c) * 4));
    float* p = S + ((size_t)cl * FQ + c) * 4;
    asm volatile("red.global.add.v4.f32 [%0], {%1,%2,%3,%4};"
                 :: "l"(p), "f"(v.x), "f"(v.y), "f"(v.z), "f"(v.w) : "memory");
}

// ---------------------------------------------------------------------------
// Elementwise post: O = relu(dinv[node]*S + R)   (float4 lanes; R may == O)
// ---------------------------------------------------------------------------
template <int FQ>
__global__ void post_kernel(const float* __restrict__ S, const float* __restrict__ R,
                            const float* __restrict__ deg, float* __restrict__ O,
                            int total4, int N)
{
    int idx = blockIdx.x * blockDim.x + threadIdx.x;
    if (idx >= total4) return;
    int node = idx / FQ;
    float dv = dinv_of(deg, node, N);
    float4 s = *reinterpret_cast<const float4*>(S + (size_t)idx * 4);
    float4 r = *reinterpret_cast<const float4*>(R + (size_t)idx * 4);
    float4 o;
    o.x = fmaxf(fmaf(dv, s.x, r.x), 0.0f);
    o.y = fmaxf(fmaf(dv, s.y, r.y), 0.0f);
    o.z = fmaxf(fmaf(dv, s.z, r.z), 0.0f);
    o.w = fmaxf(fmaf(dv, s.w, r.w), 0.0f);
    *reinterpret_cast<float4*>(O + (size_t)idx * 4) = o;
}

// ---------------------------------------------------------------------------
extern "C" void kernel_launch(void* const* d_in, const int* in_sizes, int n_in,
                              void* d_out, int out_size)
{
    const float* x   = (const float*)d_in[0];
    const int*   ei  = (const int*)  d_in[1];
    const float* w1i = (const float*)d_in[2];
    const float* w1r = (const float*)d_in[3];
    const float* b1  = (const float*)d_in[4];
    const float* w2i = (const float*)d_in[5];
    const float* w2r = (const float*)d_in[6];
    const float* b2  = (const float*)d_in[7];
    float* out = (float*)d_out;

    const int E = in_sizes[1] / 2;
    const int N = out_size / 40;
    const int* row = ei;
    const int* col = ei + E;

    float *pdeg, *arena;
    cudaGetSymbolAddress((void**)&pdeg,  g_deg);
    cudaGetSymbolAddress((void**)&arena, g_arena);

    // Arena layout — NO aliasing between concurrently-live regions.
    float* pR1 = arena;                       // [0,64N)
    float* pS1 = arena + (size_t)N * 64;      // [64N,128N)
    float* pG1 = arena + (size_t)N * 128;     // [128N,192N)   g1 (dead after scatter1)
    float* pG2 = arena + (size_t)N * 128;     // [128N,168N)   g2 (over dead g1)
    float* pS2 = arena + (size_t)N * 168;     // [168N,208N)   fresh
    float* pR2 = out;                         // R2 -> d_out; post2 in place

    // Side stream + events (created once, outside any capture).
    static cudaStream_t s2 = nullptr;
    static cudaEvent_t evA = nullptr, evB = nullptr, evC = nullptr, evD = nullptr;
    if (s2 == nullptr) {
        cudaStreamCreateWithFlags(&s2, cudaStreamNonBlocking);
        cudaEventCreateWithFlags(&evA, cudaEventDisableTiming);
        cudaEventCreateWithFlags(&evB, cudaEventDisableTiming);
        cudaEventCreateWithFlags(&evC, cudaEventDisableTiming);
        cudaEventCreateWithFlags(&evD, cudaEventDisableTiming);
    }

    const int grid = (N + 127) / 128;

    // ---- fork: R1 = x@W1r + b1 on side stream (overlaps deg/gemm1i/scatter1)
    cudaEventRecord(evA, 0);
    cudaStreamWaitEvent(s2, evA, 0);
    gemm_mma<128, 64, true, false><<<grid, 256, 0, s2>>>(
        x, nullptr, nullptr, w1r, b1, pdeg, nullptr, pR1, N);
    cudaEventRecord(evB, s2);

    // ---- main: deg, init GEMM 1, scatter 1 ----
    cudaMemsetAsync(pdeg, 0, (size_t)N * sizeof(float));
    deg_kernel<<<(E + 255) / 256, 256>>>(col, pdeg, E);

    gemm_mma<128, 64, false, false><<<grid, 256>>>(
        x, nullptr, nullptr, w1i, nullptr, pdeg, pS1, pG1, N);
    {
        int total = E * 16;
        scatter_add<16><<<(total + 255) / 256, 256>>>(row, col, pG1, pS1, total);
    }

    // ---- fork: gemm2r (fused A = relu(dinv*S1+R1)) -> d_out, after scatter1
    cudaEventRecord(evC, 0);              // scatter1 done on main
    cudaStreamWaitEvent(s2, evC, 0);      // side already has R1 in-order
    gemm_mma<64, 40, true, true><<<grid, 256, 0, s2>>>(
        nullptr, pS1, pR1, w2r, b2, pdeg, nullptr, pR2, N);
    cudaEventRecord(evD, s2);

    // ---- main: gemm2i (fused A) -> g2, S2=0 ; then scatter2 ----
    cudaStreamWaitEvent(0, evB, 0);       // need R1 before fused A-loads
    gemm_mma<64, 40, false, true><<<grid, 256>>>(
        nullptr, pS1, pR1, w2i, nullptr, pdeg, pS2, pG2, N);
    {
        int total = E * 10;
        scatter_add<10><<<(total + 255) / 256, 256>>>(row, col, pG2, pS2, total);
    }

    // ---- join; out = relu(dinv*S2 + R2) in place over d_out ----
    cudaStreamWaitEvent(0, evD, 0);
    {
        int total4 = N * 10;
        post_kernel<10><<<(total4 + 255) / 256, 256>>>(pS2, pR2, pdeg, out, total4, N);
    }
}